// round 8
// baseline (speedup 1.0000x reference)
#include <cuda_runtime.h>
#include <cstdint>
#include <math.h>

#define B_    2
#define S_    2048
#define H_    2048
#define HEADS 16
#define DH    128
#define BH    (B_*HEADS)
#define BSH   ((size_t)B_*S_*H_)
#define KT_A  64            // K=2048 / 32

// ---------------------------------------------------------------------------
// Scratch
// ---------------------------------------------------------------------------
__device__ float g_q[BSH];                      // [B,HEADS,S,DH]
__device__ float g_lnp[BSH];                    // LN output, fragment-major, rounded
__device__ float g_ctxp[BSH];                   // ctx, fragment-major, rounded
__device__ float g_qkvwP[(size_t)3*H_*H_];      // qkvw, B-fragment-major, rounded
__device__ float g_owP[(size_t)H_*H_];          // ow,   B-fragment-major, rounded

// ---------------------------------------------------------------------------
// Helpers
// ---------------------------------------------------------------------------
__device__ __forceinline__ uint32_t f2tf(float f) {
    uint32_t r;
    asm("cvt.rna.tf32.f32 %0, %1;" : "=r"(r) : "f"(f));
    return r;
}
__device__ __forceinline__ void mma_tf32(float* c, const uint32_t* a, const uint32_t* b) {
    asm volatile(
        "mma.sync.aligned.m16n8k8.row.col.f32.tf32.tf32.f32 "
        "{%0,%1,%2,%3},{%4,%5,%6,%7},{%8,%9},{%0,%1,%2,%3};\n"
        : "+f"(c[0]), "+f"(c[1]), "+f"(c[2]), "+f"(c[3])
        : "r"(a[0]), "r"(a[1]), "r"(a[2]), "r"(a[3]), "r"(b[0]), "r"(b[1]));
}
__device__ __forceinline__ void cp16(uint32_t dst, const float* src) {
    asm volatile("cp.async.cg.shared.global [%0], [%1], 16;\n" :: "r"(dst), "l"(src));
}
#define CP_COMMIT() asm volatile("cp.async.commit_group;\n")
#define CP_WAIT0()  asm volatile("cp.async.wait_group 0;\n")
#define CP_WAIT1()  asm volatile("cp.async.wait_group 1;\n")

// A-operand fragment-major index for element (m, k), K=2048:
// [m16][kt][ks][kh][lane=lr*4+lc][rh]
__device__ __forceinline__ size_t permA(int m, int k) {
    return ((size_t)((m >> 4) * KT_A + (k >> 5))) * 512
         + ((((k >> 3) & 3) * 2 + ((k >> 2) & 1)) * 64)
         + (((m & 7) << 2) + (k & 3)) * 2
         + ((m >> 3) & 1);
}

// ---------------------------------------------------------------------------
// Weight prep: w[K=2048][N] -> B-fragment-major per (n32, kt) chunk:
// [n32][kt][ks][kh][laneB=lr*4+lc][nt]  (1024 floats per chunk), tf32-rounded
// ---------------------------------------------------------------------------
__global__ void __launch_bounds__(256) prep_b(
    const float* __restrict__ w, float* __restrict__ out, int N)
{
    const int kt  = blockIdx.x;
    const int n32 = blockIdx.y;
    __shared__ float sm[32][33];
    const int tx = threadIdx.x;
    const int kl = tx >> 5, nl = tx & 31;
    #pragma unroll
    for (int i = 0; i < 32; i += 8)
        sm[kl + i][nl] = w[(size_t)(kt * 32 + kl + i) * N + n32 * 32 + nl];
    __syncthreads();
    const int laneB = tx & 31, ksh = tx >> 5;      // ksh = ks*2+kh
    const int lr = laneB >> 2, lc = laneB & 3;
    const int k_l = (ksh >> 1) * 8 + (ksh & 1) * 4 + lc;
    float4 v;
    v.x = __uint_as_float(f2tf(sm[k_l][lr]));
    v.y = __uint_as_float(f2tf(sm[k_l][8 + lr]));
    v.z = __uint_as_float(f2tf(sm[k_l][16 + lr]));
    v.w = __uint_as_float(f2tf(sm[k_l][24 + lr]));
    *(float4*)&out[((size_t)n32 * KT_A + kt) * 1024 + ksh * 128 + laneB * 4] = v;
}

// ---------------------------------------------------------------------------
// LayerNorm: writes exact y (output) + fragment-major rounded copy
// ---------------------------------------------------------------------------
__global__ void __launch_bounds__(256) ln_kernel(
    const float* __restrict__ x, const float* __restrict__ g,
    const float* __restrict__ b, float* __restrict__ y, float* __restrict__ yp)
{
    const int row = blockIdx.x;
    const float* xr = x + (size_t)row * H_;
    float s = 0.f, ss = 0.f;
    for (int i = threadIdx.x; i < H_; i += 256) {
        float t = xr[i];
        s += t; ss += t * t;
    }
    #pragma unroll
    for (int o = 16; o; o >>= 1) {
        s  += __shfl_xor_sync(0xffffffffu, s,  o);
        ss += __shfl_xor_sync(0xffffffffu, ss, o);
    }
    __shared__ float red[2][8];
    const int w = threadIdx.x >> 5, l = threadIdx.x & 31;
    if (l == 0) { red[0][w] = s; red[1][w] = ss; }
    __syncthreads();
    __shared__ float stats[2];
    if (threadIdx.x == 0) {
        float S = 0.f, SS = 0.f;
        #pragma unroll
        for (int i = 0; i < 8; i++) { S += red[0][i]; SS += red[1][i]; }
        float mu  = S / (float)H_;
        float var = SS / (float)H_ - mu * mu;
        stats[0] = mu;
        stats[1] = rsqrtf(var + 1e-12f);
    }
    __syncthreads();
    const float mu = stats[0], rstd = stats[1];
    float* yr = y + (size_t)row * H_;
    for (int i = threadIdx.x; i < H_; i += 256) {
        float v = (xr[i] - mu) * rstd * g[i] + b[i];
        yr[i] = v;
        yp[permA(row, i)] = __uint_as_float(f2tf(v));
    }
}

// ---------------------------------------------------------------------------
// TF32 mma.sync GEMM, fragment-major operands via cp.async, 3-stage pipeline.
// CTA 128x128, 256 threads (8 warps 2Mx4N, warp tile 64x32), K-tile 32.
// No LDG/STS/cvt in the main loop.
// EPI: 0 plain row-major C; 3 QKV scatter + bias.
// ---------------------------------------------------------------------------
#define STG_FLOATS 8192                 // A 4096 + B 4096 per stage (32KB)
#define GEMM_SMEM  (3 * STG_FLOATS * 4) // 98304 B

template<int EPI>
__global__ void __launch_bounds__(256, 2) mma_gemm2(
    const float* __restrict__ Ap, const float* __restrict__ Bp,
    float* __restrict__ C,
    float* __restrict__ Cq, float* __restrict__ Ck, float* __restrict__ Cv,
    const float* __restrict__ bias, int Ntot)
{
    const int m16g0 = blockIdx.y * 8;
    const int n32g0 = blockIdx.x * 4;
    const int rowBase = blockIdx.y * 128;
    const int colBase = blockIdx.x * 128;

    extern __shared__ float smf[];
    const uint32_t smemU = (uint32_t)__cvta_generic_to_shared(smf);

    const int tx = threadIdx.x;
    const int lane = tx & 31, warp = tx >> 5;
    const int wm = (warp >> 2) * 64;
    const int wn = (warp & 3) * 32;
    const int lr = lane >> 2;
    const int lc = lane & 3;

    auto loadStage = [&](int kt, int st) {
        const uint32_t sbase = smemU + st * STG_FLOATS * 4;
        #pragma unroll
        for (int i = 0; i < 8; i++) {
            const int idx = tx + i * 256;          // float4 index 0..2047
            if (idx < 1024) {                       // A half
                const int g = idx >> 7, rem = idx & 127;
                cp16(sbase + (g * 512 + rem * 4) * 4,
                     Ap + ((size_t)(m16g0 + g) * KT_A + kt) * 512 + rem * 4);
            } else {                                // B half
                const int j = idx - 1024;
                const int nb = j >> 8, rem = j & 255;
                cp16(sbase + (4096 + nb * 1024 + rem * 4) * 4,
                     Bp + ((size_t)(n32g0 + nb) * KT_A + kt) * 1024 + rem * 4);
            }
        }
    };

    float acc[4][4][4];
    #pragma unroll
    for (int i = 0; i < 4; i++)
        #pragma unroll
        for (int j = 0; j < 4; j++)
            #pragma unroll
            for (int r = 0; r < 4; r++) acc[i][j][r] = 0.f;

    loadStage(0, 0); CP_COMMIT();
    loadStage(1, 1); CP_COMMIT();

    for (int kt = 0; kt < KT_A; kt++) {
        const int st = kt % 3;
        CP_WAIT1();
        __syncthreads();
        if (kt + 2 < KT_A) { loadStage(kt + 2, (kt + 2) % 3); CP_COMMIT(); }

        const float* sf = smf + st * STG_FLOATS;
        const float* aB = sf + (warp >> 2) * 2048;       // 4 m16-chunks
        const float* bB = sf + 4096 + (warp & 3) * 1024; // 1 n32-chunk

        #pragma unroll
        for (int ks = 0; ks < 4; ks++) {
            uint32_t af[4][4];
            #pragma unroll
            for (int mt = 0; mt < 4; mt++) {
                const float* p = aB + mt * 512 + ks * 128 + lane * 2;
                float2 x0 = *(const float2*)p;          // kh=0 -> regs 0,1
                float2 x1 = *(const float2*)(p + 64);   // kh=1 -> regs 2,3
                af[mt][0] = __float_as_uint(x0.x);
                af[mt][1] = __float_as_uint(x0.y);
                af[mt][2] = __float_as_uint(x1.x);
                af[mt][3] = __float_as_uint(x1.y);
            }
            float4 b0 = *(const float4*)(bB + ks * 256 + lane * 4);        // kh=0
            float4 b1 = *(const float4*)(bB + ks * 256 + 128 + lane * 4);  // kh=1
            uint32_t bf[4][2];
            bf[0][0] = __float_as_uint(b0.x); bf[0][1] = __float_as_uint(b1.x);
            bf[1][0] = __float_as_uint(b0.y); bf[1][1] = __float_as_uint(b1.y);
            bf[2][0] = __float_as_uint(b0.z); bf[2][1] = __float_as_uint(b1.z);
            bf[3][0] = __float_as_uint(b0.w); bf[3][1] = __float_as_uint(b1.w);
            #pragma unroll
            for (int mt = 0; mt < 4; mt++)
                #pragma unroll
                for (int nt = 0; nt < 4; nt++)
                    mma_tf32(acc[mt][nt], af[mt], bf[nt]);
        }
    }

    // ---------------- epilogue ----------------
    if (EPI == 3) {
        const int whichBlk = colBase >> 11;
        float* base = (whichBlk == 0) ? Cq : (whichBlk == 1) ? Ck : Cv;
        const int h = (colBase & 2047) >> 7;
        #pragma unroll
        for (int mt = 0; mt < 4; mt++) {
            #pragma unroll
            for (int nt = 0; nt < 4; nt++) {
                const int d  = wn + nt * 8 + 2 * lc;
                const int gn = colBase + d;
                float* a = acc[mt][nt];
                #pragma unroll
                for (int r = 0; r < 2; r++) {
                    const int m = rowBase + wm + mt * 16 + lr + r * 8;
                    const int b = m >> 11, s = m & 2047;
                    float2 o2 = make_float2(a[r * 2 + 0] + bias[gn],
                                            a[r * 2 + 1] + bias[gn + 1]);
                    *(float2*)&base[((((size_t)b * 16 + h) << 11) + s) * 128 + d] = o2;
                }
            }
        }
        return;
    }

    #pragma unroll
    for (int mt = 0; mt < 4; mt++) {
        #pragma unroll
        for (int nt = 0; nt < 4; nt++) {
            const int gm = rowBase + wm + mt * 16 + lr;
            const int gn = colBase + wn + nt * 8 + 2 * lc;
            float* a = acc[mt][nt];
            #pragma unroll
            for (int r = 0; r < 2; r++)
                *(float2*)&C[(size_t)(gm + r * 8) * Ntot + gn] =
                    make_float2(a[r * 2 + 0], a[r * 2 + 1]);
        }
    }
}

// ---------------------------------------------------------------------------
// Flash attention (math unchanged) — epilogue also writes fragment-major
// rounded ctx copy for the oproj GEMM.
// ---------------------------------------------------------------------------
#define KS_STRIDE 132
#define VS_STRIDE 136
#define K_STAGE   (64*KS_STRIDE)
#define V_STAGE   (64*VS_STRIDE)
#define P_STRIDE  68

__global__ void __launch_bounds__(256, 1) flash_kernel(
    const float* __restrict__ q, const float* __restrict__ k,
    const float* __restrict__ v, const float* __restrict__ mask,
    float* __restrict__ ctx, float* __restrict__ ctxp, float scale)
{
    const int qi = gridDim.x - 1 - blockIdx.x;
    const int rowBase = qi * 128;
    const int bh = blockIdx.y;
    const int b = bh >> 4, h = bh & 15;

    const float* Q = q + (size_t)bh * S_ * DH;
    const float* K = k + (size_t)bh * S_ * DH;
    const float* V = v + (size_t)bh * S_ * DH;
    const float* mrow = mask + (size_t)b * S_;

    extern __shared__ uint32_t smfk[];
    uint32_t* Ks = smfk;
    uint32_t* Vs = smfk + 2 * K_STAGE;
    uint32_t* Ps = Vs + 2 * V_STAGE;

    const int tx = threadIdx.x;
    const int lane = tx & 31, wid = tx >> 5;
    const int lr = lane >> 2, lc = lane & 3;

    const int r0  = wid * 16 + lr;
    const int r0g = rowBase + r0;
    const int r1g = r0g + 8;

    {
        float* qs = (float*)Ks;
        #pragma unroll
        for (int i = 0; i < 16; i++) {
            int e = tx + i * 256;
            int row = e >> 5, c4 = (e & 31) * 4;
            cp16((uint32_t)__cvta_generic_to_shared(qs + row * KS_STRIDE + c4),
                 Q + (size_t)(rowBase + row) * DH + c4);
        }
        CP_COMMIT(); CP_WAIT0();
        __syncthreads();
    }
    uint32_t qf[16][4];
    {
        const float* qs = (const float*)Ks;
        #pragma unroll
        for (int ks = 0; ks < 16; ks++) {
            qf[ks][0] = f2tf(qs[(r0)     * KS_STRIDE + ks * 8 + lc]);
            qf[ks][1] = f2tf(qs[(r0 + 8) * KS_STRIDE + ks * 8 + lc]);
            qf[ks][2] = f2tf(qs[(r0)     * KS_STRIDE + ks * 8 + lc + 4]);
            qf[ks][3] = f2tf(qs[(r0 + 8) * KS_STRIDE + ks * 8 + lc + 4]);
        }
    }
    __syncthreads();

    const int jEnd = 2 * qi + 2;

    auto cpKV = [&](int j, int st) {
        float* kd = (float*)(Ks + st * K_STAGE);
        float* vd = (float*)(Vs + st * V_STAGE);
        const float* ksrc = K + (size_t)j * 64 * DH;
        const float* vsrc = V + (size_t)j * 64 * DH;
        #pragma unroll
        for (int i = 0; i < 8; i++) {
            int e = tx + i * 256;
            int row = e >> 5, c4 = (e & 31) * 4;
            cp16((uint32_t)__cvta_generic_to_shared(kd + row * KS_STRIDE + c4),
                 ksrc + (size_t)row * DH + c4);
            cp16((uint32_t)__cvta_generic_to_shared(vd + row * VS_STRIDE + c4),
                 vsrc + (size_t)row * DH + c4);
        }
    };
    auto cvtKV = [&](int st) {
        uint32_t* kd = Ks + st * K_STAGE;
        uint32_t* vd = Vs + st * V_STAGE;
        #pragma unroll
        for (int i = 0; i < 8; i++) {
            int e = tx + i * 256;
            int row = e >> 5, c4 = (e & 31) * 4;
            float4 kf = *(float4*)(kd + row * KS_STRIDE + c4);
            uint4 ku;
            ku.x = f2tf(kf.x); ku.y = f2tf(kf.y); ku.z = f2tf(kf.z); ku.w = f2tf(kf.w);
            *(uint4*)(kd + row * KS_STRIDE + c4) = ku;
            float4 vf = *(float4*)(vd + row * VS_STRIDE + c4);
            uint4 vu;
            vu.x = f2tf(vf.x); vu.y = f2tf(vf.y); vu.z = f2tf(vf.z); vu.w = f2tf(vf.w);
            *(uint4*)(vd + row * VS_STRIDE + c4) = vu;
        }
    };

    cpKV(0, 0); CP_COMMIT(); CP_WAIT0();
    __syncthreads();
    cvtKV(0);
    __syncthreads();

    float oacc[16][4];
    #pragma unroll
    for (int i = 0; i < 16; i++)
        #pragma unroll
        for (int r = 0; r < 4; r++) oacc[i][r] = 0.f;
    float m0 = -1e30f, m1 = -1e30f, l0 = 0.f, l1 = 0.f;

    uint32_t* pw = Ps + wid * 16 * P_STRIDE;

    for (int j = 0; j < jEnd; j++) {
        const int st = j & 1;
        const bool more = (j + 1 < jEnd);
        if (more) { cpKV(j + 1, st ^ 1); CP_COMMIT(); }

        float sacc[8][4];
        #pragma unroll
        for (int nt = 0; nt < 8; nt++)
            #pragma unroll
            for (int r = 0; r < 4; r++) sacc[nt][r] = 0.f;

        const uint32_t* kbase = Ks + st * K_STAGE;
        #pragma unroll
        for (int ks = 0; ks < 16; ks++) {
            uint32_t bf[8][2];
            #pragma unroll
            for (int nt = 0; nt < 8; nt++) {
                const uint32_t* p = kbase + (nt * 8 + lr) * KS_STRIDE + ks * 8 + lc;
                bf[nt][0] = p[0];
                bf[nt][1] = p[4];
            }
            #pragma unroll
            for (int nt = 0; nt < 8; nt++)
                mma_tf32(sacc[nt], qf[ks], bf[nt]);
        }

        const int keyBase = j * 64;
        float mt0 = -1e30f, mt1 = -1e30f;
        #pragma unroll
        for (int nt = 0; nt < 8; nt++) {
            const int kcol = keyBase + nt * 8 + 2 * lc;
            float2 mk = *(const float2*)&mrow[kcol];
            float s0 = sacc[nt][0] * scale + mk.x;
            float s1 = sacc[nt][1] * scale + mk.y;
            float s2 = sacc[nt][2] * scale + mk.x;
            float s3 = sacc[nt][3] * scale + mk.y;
            if (kcol     > r0g) s0 = -10000.f;
            if (kcol + 1 > r0g) s1 = -10000.f;
            if (kcol     > r1g) s2 = -10000.f;
            if (kcol + 1 > r1g) s3 = -10000.f;
            sacc[nt][0] = s0; sacc[nt][1] = s1; sacc[nt][2] = s2; sacc[nt][3] = s3;
            mt0 = fmaxf(mt0, fmaxf(s0, s1));
            mt1 = fmaxf(mt1, fmaxf(s2, s3));
        }
        mt0 = fmaxf(mt0, __shfl_xor_sync(0xffffffffu, mt0, 1));
        mt0 = fmaxf(mt0, __shfl_xor_sync(0xffffffffu, mt0, 2));
        mt1 = fmaxf(mt1, __shfl_xor_sync(0xffffffffu, mt1, 1));
        mt1 = fmaxf(mt1, __shfl_xor_sync(0xffffffffu, mt1, 2));

        const float mn0 = fmaxf(m0, mt0), mn1 = fmaxf(m1, mt1);
        const float a0 = __expf(m0 - mn0), a1 = __expf(m1 - mn1);
        m0 = mn0; m1 = mn1;

        float ts0 = 0.f, ts1 = 0.f;
        #pragma unroll
        for (int nt = 0; nt < 8; nt++) {
            float p0 = __expf(sacc[nt][0] - mn0);
            float p1 = __expf(sacc[nt][1] - mn0);
            float p2 = __expf(sacc[nt][2] - mn1);
            float p3 = __expf(sacc[nt][3] - mn1);
            sacc[nt][0] = p0; sacc[nt][1] = p1; sacc[nt][2] = p2; sacc[nt][3] = p3;
            ts0 += p0 + p1;
            ts1 += p2 + p3;
        }
        ts0 += __shfl_xor_sync(0xffffffffu, ts0, 1);
        ts0 += __shfl_xor_sync(0xffffffffu, ts0, 2);
        ts1 += __shfl_xor_sync(0xffffffffu, ts1, 1);
        ts1 += __shfl_xor_sync(0xffffffffu, ts1, 2);
        l0 = l0 * a0 + ts0;
        l1 = l1 * a1 + ts1;

        #pragma unroll
        for (int nt = 0; nt < 16; nt++) {
            oacc[nt][0] *= a0; oacc[nt][1] *= a0;
            oacc[nt][2] *= a1; oacc[nt][3] *= a1;
        }

        __syncwarp();
        #pragma unroll
        for (int nt = 0; nt < 8; nt++) {
            uint2 u0 = make_uint2(f2tf(sacc[nt][0]), f2tf(sacc[nt][1]));
            uint2 u1 = make_uint2(f2tf(sacc[nt][2]), f2tf(sacc[nt][3]));
            *(uint2*)(pw + (lr)     * P_STRIDE + nt * 8 + 2 * lc) = u0;
            *(uint2*)(pw + (lr + 8) * P_STRIDE + nt * 8 + 2 * lc) = u1;
        }
        __syncwarp();

        const uint32_t* vbase = Vs + st * V_STAGE;
        #pragma unroll
        for (int ks = 0; ks < 8; ks++) {
            uint32_t af[4];
            af[0] = pw[(lr)     * P_STRIDE + ks * 8 + lc];
            af[1] = pw[(lr + 8) * P_STRIDE + ks * 8 + lc];
            af[2] = pw[(lr)     * P_STRIDE + ks * 8 + lc + 4];
            af[3] = pw[(lr + 8) * P_STRIDE + ks * 8 + lc + 4];
            #pragma unroll
            for (int nt = 0; nt < 16; nt++) {
                const uint32_t* p = vbase + (ks * 8 + lc) * VS_STRIDE + nt * 8 + lr;
                uint32_t bf2[2] = { p[0], p[4 * VS_STRIDE] };
                mma_tf32(oacc[nt], af, bf2);
            }
        }

        if (more) {
            CP_WAIT0();
            __syncthreads();
            cvtKV(st ^ 1);
            __syncthreads();
        }
    }

    // epilogue: exact ctx [B,S,H] + fragment-major rounded copy
    const float inv0 = 1.0f / l0;
    const float inv1 = 1.0f / l1;
    const size_t o0 = ((size_t)b * S_ + r0g) * H_ + h * 128 + 2 * lc;
    const size_t o1 = ((size_t)b * S_ + r1g) * H_ + h * 128 + 2 * lc;
    #pragma unroll
    for (int nt = 0; nt < 16; nt++) {
        float v0 = oacc[nt][0] * inv0, v1 = oacc[nt][1] * inv0;
        float v2 = oacc[nt][2] * inv1, v3 = oacc[nt][3] * inv1;
        *(float2*)(ctx + o0 + nt * 8) = make_float2(v0, v1);
        *(float2*)(ctx + o1 + nt * 8) = make_float2(v2, v3);
        // perm copy: element pairs (row r0g=rh0, row r1g=rh1) are contiguous
        const int mrow_b = b * S_ + 0;   // permA uses global m over 4096 rows
        const int mg = mrow_b + r0g;     // m = b*2048 + r0g
        const int k0 = h * 128 + nt * 8 + 2 * lc;
        *(float2*)(ctxp + permA(mg, k0)) =
            make_float2(__uint_as_float(f2tf(v0)), __uint_as_float(f2tf(v2)));
        *(float2*)(ctxp + permA(mg, k0 + 1)) =
            make_float2(__uint_as_float(f2tf(v1)), __uint_as_float(f2tf(v3)));
    }
}

// ---------------------------------------------------------------------------
// kernel_launch
// ---------------------------------------------------------------------------
extern "C" void kernel_launch(void* const* d_in, const int* in_sizes, int n_in,
                              void* d_out, int out_size)
{
    const float* x    = (const float*)d_in[0];
    const float* mask = (const float*)d_in[1];
    const float* qkvw = (const float*)d_in[2];
    const float* qkvb = (const float*)d_in[3];
    const float* ow   = (const float*)d_in[4];
    const float* nw   = (const float*)d_in[5];
    const float* nb   = (const float*)d_in[6];

    float* out     = (float*)d_out;
    float* out_o   = out;
    float* out_k   = out + 1 * BSH;
    float* out_v   = out + 2 * BSH;
    float* out_ctx = out + 3 * BSH;
    float* out_ln  = out + 4 * BSH;

    float *q, *lnp, *ctxp, *qkvwP, *owP;
    cudaGetSymbolAddress((void**)&q,     g_q);
    cudaGetSymbolAddress((void**)&lnp,   g_lnp);
    cudaGetSymbolAddress((void**)&ctxp,  g_ctxp);
    cudaGetSymbolAddress((void**)&qkvwP, g_qkvwP);
    cudaGetSymbolAddress((void**)&owP,   g_owP);

    const int FLASH_SMEM = (2 * K_STAGE + 2 * V_STAGE + 8 * 16 * P_STRIDE) * 4;

    cudaFuncSetAttribute(mma_gemm2<3>, cudaFuncAttributeMaxDynamicSharedMemorySize, GEMM_SMEM);
    cudaFuncSetAttribute(mma_gemm2<0>, cudaFuncAttributeMaxDynamicSharedMemorySize, GEMM_SMEM);
    cudaFuncSetAttribute(flash_kernel, cudaFuncAttributeMaxDynamicSharedMemorySize, FLASH_SMEM);

    const float scale = 1.0f / sqrtf((float)DH);

    // 0. Weight prep (fragment-major, tf32-rounded)
    prep_b<<<dim3(KT_A, 3 * H_ / 32), 256>>>(qkvw, qkvwP, 3 * H_);
    prep_b<<<dim3(KT_A, H_ / 32), 256>>>(ow, owP, H_);

    // 1. LayerNorm -> out_ln + lnp (fragment-major rounded)
    ln_kernel<<<B_ * S_, 256>>>(x, nw, nb, out_ln, lnp);

    // 2. QKV GEMM + bias, scatter q/k/v in [B,H,S,dh]
    mma_gemm2<3><<<dim3(48, 32), 256, GEMM_SMEM>>>(
        lnp, qkvwP, nullptr, q, out_k, out_v, qkvb, 3 * H_);

    // 3. Flash attention -> out_ctx + ctxp
    flash_kernel<<<dim3(16, BH), 256, FLASH_SMEM>>>(
        q, out_k, out_v, mask, out_ctx, ctxp, scale);

    // 4. Output projection
    mma_gemm2<0><<<dim3(16, 32), 256, GEMM_SMEM>>>(
        ctxp, owP, out_o, nullptr, nullptr, nullptr, nullptr, H_);
}

// round 9
// speedup vs baseline: 1.4459x; 1.4459x over previous
#include <cuda_runtime.h>
#include <cuda_fp16.h>
#include <cstdint>
#include <math.h>

#define B_    2
#define S_    2048
#define H_    2048
#define HEADS 16
#define DH    128
#define BH    (B_*HEADS)
#define BSH   ((size_t)B_*S_*H_)
#define KT_A  64

// ---------------------------------------------------------------------------
__device__ float  g_q[BSH];                      // exact q [B,H,S,dh]
__device__ __half g_lnp[BSH];                    // LN out, A-frag fp16
__device__ __half g_ctxp[BSH];                   // ctx,    A-frag fp16
__device__ __half g_qkvwP[(size_t)3*H_*H_];      // qkvw, B-frag fp16
__device__ __half g_owP[(size_t)H_*H_];          // ow,   B-frag fp16

// ---------------------------------------------------------------------------
__device__ __forceinline__ uint32_t f2tf(float f) {
    uint32_t r;
    asm("cvt.rna.tf32.f32 %0, %1;" : "=r"(r) : "f"(f));
    return r;
}
__device__ __forceinline__ void mma_tf32(float* c, const uint32_t* a, const uint32_t* b) {
    asm volatile(
        "mma.sync.aligned.m16n8k8.row.col.f32.tf32.tf32.f32 "
        "{%0,%1,%2,%3},{%4,%5,%6,%7},{%8,%9},{%0,%1,%2,%3};\n"
        : "+f"(c[0]), "+f"(c[1]), "+f"(c[2]), "+f"(c[3])
        : "r"(a[0]), "r"(a[1]), "r"(a[2]), "r"(a[3]), "r"(b[0]), "r"(b[1]));
}
__device__ __forceinline__ void mma_f16(float* c, const uint32_t* a, const uint32_t* b) {
    asm volatile(
        "mma.sync.aligned.m16n8k16.row.col.f32.f16.f16.f32 "
        "{%0,%1,%2,%3},{%4,%5,%6,%7},{%8,%9},{%0,%1,%2,%3};\n"
        : "+f"(c[0]), "+f"(c[1]), "+f"(c[2]), "+f"(c[3])
        : "r"(a[0]), "r"(a[1]), "r"(a[2]), "r"(a[3]), "r"(b[0]), "r"(b[1]));
}
__device__ __forceinline__ void cp16(uint32_t dst, const void* src) {
    asm volatile("cp.async.cg.shared.global [%0], [%1], 16;\n" :: "r"(dst), "l"(src));
}
#define CP_COMMIT() asm volatile("cp.async.commit_group;\n")
#define CP_WAIT0()  asm volatile("cp.async.wait_group 0;\n")
#define CP_WAIT1()  asm volatile("cp.async.wait_group 1;\n")

// fp16 A-fragment index (m16n8k16), K=2048: per (m16,kt32) 512 halfs
__device__ __forceinline__ size_t afragH(int m, int k) {
    return ((size_t)((m >> 4) * KT_A + (k >> 5))) * 512
         + (((k >> 4) & 1) * 256)
         + (((m & 7) * 4 + ((k >> 1) & 3)) * 8)
         + ((((k >> 3) & 1) * 2 + ((m >> 3) & 1)) * 2)
         + (k & 1);
}

// ---------------------------------------------------------------------------
// Weight prep: w[K][N] -> fp16 B-frag chunks [n32][kt]: 1024 halfs
// ---------------------------------------------------------------------------
__global__ void __launch_bounds__(256) prep_b(
    const float* __restrict__ w, __half* __restrict__ out, int N)
{
    const int kt = blockIdx.x, n32 = blockIdx.y;
    __shared__ float sm[32][33];
    const int tx = threadIdx.x;
    const int kl = tx >> 5, nl = tx & 31;
    #pragma unroll
    for (int i = 0; i < 32; i += 8)
        sm[kl + i][nl] = w[(size_t)(kt * 32 + kl + i) * N + n32 * 32 + nl];
    __syncthreads();
    const size_t base = ((size_t)n32 * KT_A + kt) * 1024;
    #pragma unroll
    for (int e = tx; e < 1024; e += 256) {
        const int k = e >> 5, n = e & 31;
        const int off = ((k >> 4) * 512) + (((k >> 3) & 1) * 256)
                      + (((n & 7) * 4 + ((k >> 1) & 3)) * 8)
                      + ((n >> 3) * 2) + (k & 1);
        out[base + off] = __float2half_rn(sm[k][n]);
    }
}

// ---------------------------------------------------------------------------
// LayerNorm: exact y + fp16 A-frag copy
// ---------------------------------------------------------------------------
__global__ void __launch_bounds__(256) ln_kernel(
    const float* __restrict__ x, const float* __restrict__ g,
    const float* __restrict__ b, float* __restrict__ y, __half* __restrict__ yp)
{
    const int row = blockIdx.x;
    const float* xr = x + (size_t)row * H_;
    float s = 0.f, ss = 0.f;
    for (int i = threadIdx.x; i < H_; i += 256) {
        float t = xr[i];
        s += t; ss += t * t;
    }
    #pragma unroll
    for (int o = 16; o; o >>= 1) {
        s  += __shfl_xor_sync(0xffffffffu, s,  o);
        ss += __shfl_xor_sync(0xffffffffu, ss, o);
    }
    __shared__ float red[2][8];
    const int w = threadIdx.x >> 5, l = threadIdx.x & 31;
    if (l == 0) { red[0][w] = s; red[1][w] = ss; }
    __syncthreads();
    __shared__ float stats[2];
    if (threadIdx.x == 0) {
        float S = 0.f, SS = 0.f;
        #pragma unroll
        for (int i = 0; i < 8; i++) { S += red[0][i]; SS += red[1][i]; }
        float mu  = S / (float)H_;
        float var = SS / (float)H_ - mu * mu;
        stats[0] = mu;
        stats[1] = rsqrtf(var + 1e-12f);
    }
    __syncthreads();
    const float mu = stats[0], rstd = stats[1];
    float* yr = y + (size_t)row * H_;
    for (int i = threadIdx.x; i < H_; i += 256) {
        float v = (xr[i] - mu) * rstd * g[i] + b[i];
        yr[i] = v;
        yp[afragH(row, i)] = __float2half_rn(v);
    }
}

// ---------------------------------------------------------------------------
// FP16 mma.sync GEMM, fragment-major operands, 3-stage cp.async pipeline.
// CTA 128x128, 256 threads, warp 64x32, K-tile 32 (2 k16 steps).
// EPI: 0 plain C; 3 QKV scatter + bias (q exact fp32 + exact k/v).
// ---------------------------------------------------------------------------
#define STG_HALFS 8192                    // A 4096 + B 4096 halfs = 16KB
#define GEMM_SMEM (3 * STG_HALFS * 2)     // 49152 B

template<int EPI>
__global__ void __launch_bounds__(256, 2) mma_gemm2(
    const __half* __restrict__ Ap, const __half* __restrict__ Bp,
    float* __restrict__ C,
    float* __restrict__ Cq, float* __restrict__ Ck, float* __restrict__ Cv,
    const float* __restrict__ bias, int Ntot)
{
    const int m16g0 = blockIdx.y * 8;
    const int n32g0 = blockIdx.x * 4;
    const int rowBase = blockIdx.y * 128;
    const int colBase = blockIdx.x * 128;

    extern __shared__ __half smh[];
    const uint32_t smemU = (uint32_t)__cvta_generic_to_shared(smh);

    const int tx = threadIdx.x;
    const int lane = tx & 31, warp = tx >> 5;
    const int wm = (warp >> 2) * 64;
    const int wn = (warp & 3) * 32;
    const int lr = lane >> 2;
    const int lc = lane & 3;

    auto loadStage = [&](int kt, int st) {
        const uint32_t sbase = smemU + st * STG_HALFS * 2;
        #pragma unroll
        for (int i = 0; i < 4; i++) {
            const int idx = tx + i * 256;          // uint4 index 0..1023
            if (idx < 512) {                        // A: 8 chunks x 64 uint4
                const int g = idx >> 6, rem = idx & 63;
                cp16(sbase + idx * 16,
                     Ap + ((size_t)(m16g0 + g) * KT_A + kt) * 512 + rem * 8);
            } else {                                // B: 4 chunks x 128 uint4
                const int j = idx - 512;
                const int nb = j >> 7, rem = j & 127;
                cp16(sbase + idx * 16,
                     Bp + ((size_t)(n32g0 + nb) * KT_A + kt) * 1024 + rem * 8);
            }
        }
    };

    float acc[4][4][4];
    #pragma unroll
    for (int i = 0; i < 4; i++)
        #pragma unroll
        for (int j = 0; j < 4; j++)
            #pragma unroll
            for (int r = 0; r < 4; r++) acc[i][j][r] = 0.f;

    loadStage(0, 0); CP_COMMIT();
    loadStage(1, 1); CP_COMMIT();

    for (int kt = 0; kt < KT_A; kt++) {
        const int st = kt % 3;
        CP_WAIT1();
        __syncthreads();
        if (kt + 2 < KT_A) { loadStage(kt + 2, (kt + 2) % 3); CP_COMMIT(); }

        const __half* sf = smh + st * STG_HALFS;
        const __half* aB = sf + (warp >> 2) * 2048;       // 4 m16-chunks
        const __half* bB = sf + 4096 + (warp & 3) * 1024; // 1 n32-chunk

        #pragma unroll
        for (int ks = 0; ks < 2; ks++) {
            uint32_t af[4][4];
            #pragma unroll
            for (int mt = 0; mt < 4; mt++) {
                uint4 t = *(const uint4*)(aB + mt * 512 + ks * 256 + lane * 8);
                af[mt][0] = t.x; af[mt][1] = t.y; af[mt][2] = t.z; af[mt][3] = t.w;
            }
            uint4 tb0 = *(const uint4*)(bB + ks * 512 + lane * 8);
            uint4 tb1 = *(const uint4*)(bB + ks * 512 + 256 + lane * 8);
            uint32_t bf[4][2];
            bf[0][0] = tb0.x; bf[0][1] = tb1.x;
            bf[1][0] = tb0.y; bf[1][1] = tb1.y;
            bf[2][0] = tb0.z; bf[2][1] = tb1.z;
            bf[3][0] = tb0.w; bf[3][1] = tb1.w;
            #pragma unroll
            for (int mt = 0; mt < 4; mt++)
                #pragma unroll
                for (int nt = 0; nt < 4; nt++)
                    mma_f16(acc[mt][nt], af[mt], bf[nt]);
        }
    }

    if (EPI == 3) {
        const int whichBlk = colBase >> 11;
        float* base = (whichBlk == 0) ? Cq : (whichBlk == 1) ? Ck : Cv;
        const int h = (colBase & 2047) >> 7;
        #pragma unroll
        for (int mt = 0; mt < 4; mt++) {
            #pragma unroll
            for (int nt = 0; nt < 4; nt++) {
                const int d  = wn + nt * 8 + 2 * lc;
                const int gn = colBase + d;
                float* a = acc[mt][nt];
                #pragma unroll
                for (int r = 0; r < 2; r++) {
                    const int m = rowBase + wm + mt * 16 + lr + r * 8;
                    const int b = m >> 11, s = m & 2047;
                    float2 o2 = make_float2(a[r * 2 + 0] + bias[gn],
                                            a[r * 2 + 1] + bias[gn + 1]);
                    *(float2*)&base[((((size_t)b * 16 + h) << 11) + s) * 128 + d] = o2;
                }
            }
        }
        return;
    }

    #pragma unroll
    for (int mt = 0; mt < 4; mt++) {
        #pragma unroll
        for (int nt = 0; nt < 4; nt++) {
            const int gm = rowBase + wm + mt * 16 + lr;
            const int gn = colBase + wn + nt * 8 + 2 * lc;
            float* a = acc[mt][nt];
            #pragma unroll
            for (int r = 0; r < 2; r++)
                *(float2*)&C[(size_t)(gm + r * 8) * Ntot + gn] =
                    make_float2(a[r * 2 + 0], a[r * 2 + 1]);
        }
    }
}

// ---------------------------------------------------------------------------
// Flash attention (identical math to R7) — ctx frag copy now fp16
// ---------------------------------------------------------------------------
#define KS_STRIDE 132
#define VS_STRIDE 136
#define K_STAGE   (64*KS_STRIDE)
#define V_STAGE   (64*VS_STRIDE)
#define P_STRIDE  68

__global__ void __launch_bounds__(256, 1) flash_kernel(
    const float* __restrict__ q, const float* __restrict__ k,
    const float* __restrict__ v, const float* __restrict__ mask,
    float* __restrict__ ctx, __half* __restrict__ ctxp, float scale)
{
    const int qi = gridDim.x - 1 - blockIdx.x;
    const int rowBase = qi * 128;
    const int bh = blockIdx.y;
    const int b = bh >> 4, h = bh & 15;

    const float* Q = q + (size_t)bh * S_ * DH;
    const float* K = k + (size_t)bh * S_ * DH;
    const float* V = v + (size_t)bh * S_ * DH;
    const float* mrow = mask + (size_t)b * S_;

    extern __shared__ uint32_t smfk[];
    uint32_t* Ks = smfk;
    uint32_t* Vs = smfk + 2 * K_STAGE;
    uint32_t* Ps = Vs + 2 * V_STAGE;

    const int tx = threadIdx.x;
    const int lane = tx & 31, wid = tx >> 5;
    const int lr = lane >> 2, lc = lane & 3;

    const int r0  = wid * 16 + lr;
    const int r0g = rowBase + r0;
    const int r1g = r0g + 8;

    {
        float* qs = (float*)Ks;
        #pragma unroll
        for (int i = 0; i < 16; i++) {
            int e = tx + i * 256;
            int row = e >> 5, c4 = (e & 31) * 4;
            cp16((uint32_t)__cvta_generic_to_shared(qs + row * KS_STRIDE + c4),
                 Q + (size_t)(rowBase + row) * DH + c4);
        }
        CP_COMMIT(); CP_WAIT0();
        __syncthreads();
    }
    uint32_t qf[16][4];
    {
        const float* qs = (const float*)Ks;
        #pragma unroll
        for (int ks = 0; ks < 16; ks++) {
            qf[ks][0] = f2tf(qs[(r0)     * KS_STRIDE + ks * 8 + lc]);
            qf[ks][1] = f2tf(qs[(r0 + 8) * KS_STRIDE + ks * 8 + lc]);
            qf[ks][2] = f2tf(qs[(r0)     * KS_STRIDE + ks * 8 + lc + 4]);
            qf[ks][3] = f2tf(qs[(r0 + 8) * KS_STRIDE + ks * 8 + lc + 4]);
        }
    }
    __syncthreads();

    const int jEnd = 2 * qi + 2;

    auto cpKV = [&](int j, int st) {
        float* kd = (float*)(Ks + st * K_STAGE);
        float* vd = (float*)(Vs + st * V_STAGE);
        const float* ksrc = K + (size_t)j * 64 * DH;
        const float* vsrc = V + (size_t)j * 64 * DH;
        #pragma unroll
        for (int i = 0; i < 8; i++) {
            int e = tx + i * 256;
            int row = e >> 5, c4 = (e & 31) * 4;
            cp16((uint32_t)__cvta_generic_to_shared(kd + row * KS_STRIDE + c4),
                 ksrc + (size_t)row * DH + c4);
            cp16((uint32_t)__cvta_generic_to_shared(vd + row * VS_STRIDE + c4),
                 vsrc + (size_t)row * DH + c4);
        }
    };
    auto cvtKV = [&](int st) {
        uint32_t* kd = Ks + st * K_STAGE;
        uint32_t* vd = Vs + st * V_STAGE;
        #pragma unroll
        for (int i = 0; i < 8; i++) {
            int e = tx + i * 256;
            int row = e >> 5, c4 = (e & 31) * 4;
            float4 kf = *(float4*)(kd + row * KS_STRIDE + c4);
            uint4 ku;
            ku.x = f2tf(kf.x); ku.y = f2tf(kf.y); ku.z = f2tf(kf.z); ku.w = f2tf(kf.w);
            *(uint4*)(kd + row * KS_STRIDE + c4) = ku;
            float4 vf = *(float4*)(vd + row * VS_STRIDE + c4);
            uint4 vu;
            vu.x = f2tf(vf.x); vu.y = f2tf(vf.y); vu.z = f2tf(vf.z); vu.w = f2tf(vf.w);
            *(uint4*)(vd + row * VS_STRIDE + c4) = vu;
        }
    };

    cpKV(0, 0); CP_COMMIT(); CP_WAIT0();
    __syncthreads();
    cvtKV(0);
    __syncthreads();

    float oacc[16][4];
    #pragma unroll
    for (int i = 0; i < 16; i++)
        #pragma unroll
        for (int r = 0; r < 4; r++) oacc[i][r] = 0.f;
    float m0 = -1e30f, m1 = -1e30f, l0 = 0.f, l1 = 0.f;

    uint32_t* pw = Ps + wid * 16 * P_STRIDE;

    for (int j = 0; j < jEnd; j++) {
        const int st = j & 1;
        const bool more = (j + 1 < jEnd);
        if (more) { cpKV(j + 1, st ^ 1); CP_COMMIT(); }

        float sacc[8][4];
        #pragma unroll
        for (int nt = 0; nt < 8; nt++)
            #pragma unroll
            for (int r = 0; r < 4; r++) sacc[nt][r] = 0.f;

        const uint32_t* kbase = Ks + st * K_STAGE;
        #pragma unroll
        for (int ks = 0; ks < 16; ks++) {
            uint32_t bf[8][2];
            #pragma unroll
            for (int nt = 0; nt < 8; nt++) {
                const uint32_t* p = kbase + (nt * 8 + lr) * KS_STRIDE + ks * 8 + lc;
                bf[nt][0] = p[0];
                bf[nt][1] = p[4];
            }
            #pragma unroll
            for (int nt = 0; nt < 8; nt++)
                mma_tf32(sacc[nt], qf[ks], bf[nt]);
        }

        const int keyBase = j * 64;
        float mt0 = -1e30f, mt1 = -1e30f;
        #pragma unroll
        for (int nt = 0; nt < 8; nt++) {
            const int kcol = keyBase + nt * 8 + 2 * lc;
            float2 mk = *(const float2*)&mrow[kcol];
            float s0 = sacc[nt][0] * scale + mk.x;
            float s1 = sacc[nt][1] * scale + mk.y;
            float s2 = sacc[nt][2] * scale + mk.x;
            float s3 = sacc[nt][3] * scale + mk.y;
            if (kcol     > r0g) s0 = -10000.f;
            if (kcol + 1 > r0g) s1 = -10000.f;
            if (kcol     > r1g) s2 = -10000.f;
            if (kcol + 1 > r1g) s3 = -10000.f;
            sacc[nt][0] = s0; sacc[nt][1] = s1; sacc[nt][2] = s2; sacc[nt][3] = s3;
            mt0 = fmaxf(mt0, fmaxf(s0, s1));
            mt1 = fmaxf(mt1, fmaxf(s2, s3));
        }
        mt0 = fmaxf(mt0, __shfl_xor_sync(0xffffffffu, mt0, 1));
        mt0 = fmaxf(mt0, __shfl_xor_sync(0xffffffffu, mt0, 2));
        mt1 = fmaxf(mt1, __shfl_xor_sync(0xffffffffu, mt1, 1));
        mt1 = fmaxf(mt1, __shfl_xor_sync(0xffffffffu, mt1, 2));

        const float mn0 = fmaxf(m0, mt0), mn1 = fmaxf(m1, mt1);
        const float a0 = __expf(m0 - mn0), a1 = __expf(m1 - mn1);
        m0 = mn0; m1 = mn1;

        float ts0 = 0.f, ts1 = 0.f;
        #pragma unroll
        for (int nt = 0; nt < 8; nt++) {
            float p0 = __expf(sacc[nt][0] - mn0);
            float p1 = __expf(sacc[nt][1] - mn0);
            float p2 = __expf(sacc[nt][2] - mn1);
            float p3 = __expf(sacc[nt][3] - mn1);
            sacc[nt][0] = p0; sacc[nt][1] = p1; sacc[nt][2] = p2; sacc[nt][3] = p3;
            ts0 += p0 + p1;
            ts1 += p2 + p3;
        }
        ts0 += __shfl_xor_sync(0xffffffffu, ts0, 1);
        ts0 += __shfl_xor_sync(0xffffffffu, ts0, 2);
        ts1 += __shfl_xor_sync(0xffffffffu, ts1, 1);
        ts1 += __shfl_xor_sync(0xffffffffu, ts1, 2);
        l0 = l0 * a0 + ts0;
        l1 = l1 * a1 + ts1;

        #pragma unroll
        for (int nt = 0; nt < 16; nt++) {
            oacc[nt][0] *= a0; oacc[nt][1] *= a0;
            oacc[nt][2] *= a1; oacc[nt][3] *= a1;
        }

        __syncwarp();
        #pragma unroll
        for (int nt = 0; nt < 8; nt++) {
            uint2 u0 = make_uint2(f2tf(sacc[nt][0]), f2tf(sacc[nt][1]));
            uint2 u1 = make_uint2(f2tf(sacc[nt][2]), f2tf(sacc[nt][3]));
            *(uint2*)(pw + (lr)     * P_STRIDE + nt * 8 + 2 * lc) = u0;
            *(uint2*)(pw + (lr + 8) * P_STRIDE + nt * 8 + 2 * lc) = u1;
        }
        __syncwarp();

        const uint32_t* vbase = Vs + st * V_STAGE;
        #pragma unroll
        for (int ks = 0; ks < 8; ks++) {
            uint32_t af[4];
            af[0] = pw[(lr)     * P_STRIDE + ks * 8 + lc];
            af[1] = pw[(lr + 8) * P_STRIDE + ks * 8 + lc];
            af[2] = pw[(lr)     * P_STRIDE + ks * 8 + lc + 4];
            af[3] = pw[(lr + 8) * P_STRIDE + ks * 8 + lc + 4];
            #pragma unroll
            for (int nt = 0; nt < 16; nt++) {
                const uint32_t* p = vbase + (ks * 8 + lc) * VS_STRIDE + nt * 8 + lr;
                uint32_t bf2[2] = { p[0], p[4 * VS_STRIDE] };
                mma_tf32(oacc[nt], af, bf2);
            }
        }

        if (more) {
            CP_WAIT0();
            __syncthreads();
            cvtKV(st ^ 1);
            __syncthreads();
        }
    }

    // epilogue: exact ctx [B,S,H] + fp16 A-frag copy (v0,v1,v2,v3 contiguous)
    const float inv0 = 1.0f / l0;
    const float inv1 = 1.0f / l1;
    const size_t o0 = ((size_t)b * S_ + r0g) * H_ + h * 128 + 2 * lc;
    const size_t o1 = ((size_t)b * S_ + r1g) * H_ + h * 128 + 2 * lc;
    const int mg = b * S_ + r0g;
    #pragma unroll
    for (int nt = 0; nt < 16; nt++) {
        float v0 = oacc[nt][0] * inv0, v1 = oacc[nt][1] * inv0;
        float v2 = oacc[nt][2] * inv1, v3 = oacc[nt][3] * inv1;
        *(float2*)(ctx + o0 + nt * 8) = make_float2(v0, v1);
        *(float2*)(ctx + o1 + nt * 8) = make_float2(v2, v3);
        const int k0 = h * 128 + nt * 8 + 2 * lc;
        __half2 h01 = __floats2half2_rn(v0, v1);
        __half2 h23 = __floats2half2_rn(v2, v3);
        uint2 u = make_uint2(*(uint32_t*)&h01, *(uint32_t*)&h23);
        *(uint2*)&ctxp[afragH(mg, k0)] = u;
    }
}

// ---------------------------------------------------------------------------
extern "C" void kernel_launch(void* const* d_in, const int* in_sizes, int n_in,
                              void* d_out, int out_size)
{
    const float* x    = (const float*)d_in[0];
    const float* mask = (const float*)d_in[1];
    const float* qkvw = (const float*)d_in[2];
    const float* qkvb = (const float*)d_in[3];
    const float* ow   = (const float*)d_in[4];
    const float* nw   = (const float*)d_in[5];
    const float* nb   = (const float*)d_in[6];

    float* out     = (float*)d_out;
    float* out_o   = out;
    float* out_k   = out + 1 * BSH;
    float* out_v   = out + 2 * BSH;
    float* out_ctx = out + 3 * BSH;
    float* out_ln  = out + 4 * BSH;

    float* q;
    __half *lnp, *ctxp, *qkvwP, *owP;
    cudaGetSymbolAddress((void**)&q,     g_q);
    cudaGetSymbolAddress((void**)&lnp,   g_lnp);
    cudaGetSymbolAddress((void**)&ctxp,  g_ctxp);
    cudaGetSymbolAddress((void**)&qkvwP, g_qkvwP);
    cudaGetSymbolAddress((void**)&owP,   g_owP);

    const int FLASH_SMEM = (2 * K_STAGE + 2 * V_STAGE + 8 * 16 * P_STRIDE) * 4;

    cudaFuncSetAttribute(mma_gemm2<3>, cudaFuncAttributeMaxDynamicSharedMemorySize, GEMM_SMEM);
    cudaFuncSetAttribute(mma_gemm2<0>, cudaFuncAttributeMaxDynamicSharedMemorySize, GEMM_SMEM);
    cudaFuncSetAttribute(flash_kernel, cudaFuncAttributeMaxDynamicSharedMemorySize, FLASH_SMEM);

    const float scale = 1.0f / sqrtf((float)DH);

    prep_b<<<dim3(KT_A, 3 * H_ / 32), 256>>>(qkvw, qkvwP, 3 * H_);
    prep_b<<<dim3(KT_A, H_ / 32), 256>>>(ow, owP, H_);

    ln_kernel<<<B_ * S_, 256>>>(x, nw, nb, out_ln, lnp);

    mma_gemm2<3><<<dim3(48, 32), 256, GEMM_SMEM>>>(
        lnp, qkvwP, nullptr, q, out_k, out_v, qkvb, 3 * H_);

    flash_kernel<<<dim3(16, BH), 256, FLASH_SMEM>>>(
        q, out_k, out_v, mask, out_ctx, ctxp, scale);

    mma_gemm2<0><<<dim3(16, 32), 256, GEMM_SMEM>>>(
        ctxp, owP, out_o, nullptr, nullptr, nullptr, nullptr, H_);
}

// round 10
// speedup vs baseline: 1.9115x; 1.3220x over previous
#include <cuda_runtime.h>
#include <cuda_fp16.h>
#include <cstdint>
#include <math.h>

#define B_    2
#define S_    2048
#define H_    2048
#define HEADS 16
#define DH    128
#define BH    (B_*HEADS)
#define BSH   ((size_t)B_*S_*H_)
#define KT_A  64

// ---------------------------------------------------------------------------
__device__ __half g_qfr[BSH];                    // Q flash-A-frags fp16
__device__ __half g_kfr[BSH];                    // K flash-B-frags fp16
__device__ __half g_vfr[BSH];                    // V flash-B-frags fp16
__device__ __half g_lnp[BSH];                    // LN out, GEMM-A-frag fp16
__device__ __half g_ctxp[BSH];                   // ctx,    GEMM-A-frag fp16
__device__ __half g_qkvwP[(size_t)3*H_*H_];      // qkvw, B-frag fp16
__device__ __half g_owP[(size_t)H_*H_];          // ow,   B-frag fp16

// ---------------------------------------------------------------------------
__device__ __forceinline__ uint32_t h2u(__half2 h) { return *(uint32_t*)&h; }
__device__ __forceinline__ void mma_f16(float* c, const uint32_t* a, const uint32_t* b) {
    asm volatile(
        "mma.sync.aligned.m16n8k16.row.col.f32.f16.f16.f32 "
        "{%0,%1,%2,%3},{%4,%5,%6,%7},{%8,%9},{%0,%1,%2,%3};\n"
        : "+f"(c[0]), "+f"(c[1]), "+f"(c[2]), "+f"(c[3])
        : "r"(a[0]), "r"(a[1]), "r"(a[2]), "r"(a[3]), "r"(b[0]), "r"(b[1]));
}
__device__ __forceinline__ void cp16(uint32_t dst, const void* src) {
    asm volatile("cp.async.cg.shared.global [%0], [%1], 16;\n" :: "r"(dst), "l"(src));
}
#define CP_COMMIT() asm volatile("cp.async.commit_group;\n")
#define CP_WAIT0()  asm volatile("cp.async.wait_group 0;\n")
#define CP_WAIT1()  asm volatile("cp.async.wait_group 1;\n")

// fp16 GEMM A-fragment index (m16n8k16), K=2048
__device__ __forceinline__ size_t afragH(int m, int k) {
    return ((size_t)((m >> 4) * KT_A + (k >> 5))) * 512
         + (((k >> 4) & 1) * 256)
         + (((m & 7) * 4 + ((k >> 1) & 3)) * 8)
         + ((((k >> 3) & 1) * 2 + ((m >> 3) & 1)) * 2)
         + (k & 1);
}

// ---------------------------------------------------------------------------
// Weight prep: w[K][N] -> fp16 B-frag chunks [n32][kt]: 1024 halfs
// ---------------------------------------------------------------------------
__global__ void __launch_bounds__(256) prep_b(
    const float* __restrict__ w, __half* __restrict__ out, int N)
{
    const int kt = blockIdx.x, n32 = blockIdx.y;
    __shared__ float sm[32][33];
    const int tx = threadIdx.x;
    const int kl = tx >> 5, nl = tx & 31;
    #pragma unroll
    for (int i = 0; i < 32; i += 8)
        sm[kl + i][nl] = w[(size_t)(kt * 32 + kl + i) * N + n32 * 32 + nl];
    __syncthreads();
    const size_t base = ((size_t)n32 * KT_A + kt) * 1024;
    #pragma unroll
    for (int e = tx; e < 1024; e += 256) {
        const int k = e >> 5, n = e & 31;
        const int off = ((k >> 4) * 512) + (((k >> 3) & 1) * 256)
                      + (((n & 7) * 4 + ((k >> 1) & 3)) * 8)
                      + ((n >> 3) * 2) + (k & 1);
        out[base + off] = __float2half_rn(sm[k][n]);
    }
}

// ---------------------------------------------------------------------------
// LayerNorm: exact y + fp16 GEMM-A-frag copy
// ---------------------------------------------------------------------------
__global__ void __launch_bounds__(256) ln_kernel(
    const float* __restrict__ x, const float* __restrict__ g,
    const float* __restrict__ b, float* __restrict__ y, __half* __restrict__ yp)
{
    const int row = blockIdx.x;
    const float* xr = x + (size_t)row * H_;
    float s = 0.f, ss = 0.f;
    for (int i = threadIdx.x; i < H_; i += 256) {
        float t = xr[i];
        s += t; ss += t * t;
    }
    #pragma unroll
    for (int o = 16; o; o >>= 1) {
        s  += __shfl_xor_sync(0xffffffffu, s,  o);
        ss += __shfl_xor_sync(0xffffffffu, ss, o);
    }
    __shared__ float red[2][8];
    const int w = threadIdx.x >> 5, l = threadIdx.x & 31;
    if (l == 0) { red[0][w] = s; red[1][w] = ss; }
    __syncthreads();
    __shared__ float stats[2];
    if (threadIdx.x == 0) {
        float S = 0.f, SS = 0.f;
        #pragma unroll
        for (int i = 0; i < 8; i++) { S += red[0][i]; SS += red[1][i]; }
        float mu  = S / (float)H_;
        float var = SS / (float)H_ - mu * mu;
        stats[0] = mu;
        stats[1] = rsqrtf(var + 1e-12f);
    }
    __syncthreads();
    const float mu = stats[0], rstd = stats[1];
    float* yr = y + (size_t)row * H_;
    for (int i = threadIdx.x; i < H_; i += 256) {
        float v = (xr[i] - mu) * rstd * g[i] + b[i];
        yr[i] = v;
        yp[afragH(row, i)] = __float2half_rn(v);
    }
}

// ---------------------------------------------------------------------------
// FP16 mma.sync GEMM (as R9), EPI 3 now scatters flash-fragment q/k/v.
// ---------------------------------------------------------------------------
#define STG_HALFS 8192
#define GEMM_SMEM (3 * STG_HALFS * 2)

template<int EPI>
__global__ void __launch_bounds__(256, 2) mma_gemm2(
    const __half* __restrict__ Ap, const __half* __restrict__ Bp,
    float* __restrict__ C,
    __half* __restrict__ Qf, float* __restrict__ Ck, float* __restrict__ Cv,
    __half* __restrict__ Kf, __half* __restrict__ Vf,
    const float* __restrict__ bias, int Ntot)
{
    const int m16g0 = blockIdx.y * 8;
    const int n32g0 = blockIdx.x * 4;
    const int rowBase = blockIdx.y * 128;
    const int colBase = blockIdx.x * 128;

    extern __shared__ __half smh[];
    const uint32_t smemU = (uint32_t)__cvta_generic_to_shared(smh);

    const int tx = threadIdx.x;
    const int lane = tx & 31, warp = tx >> 5;
    const int wm = (warp >> 2) * 64;
    const int wn = (warp & 3) * 32;
    const int lr = lane >> 2;
    const int lc = lane & 3;

    auto loadStage = [&](int kt, int st) {
        const uint32_t sbase = smemU + st * STG_HALFS * 2;
        #pragma unroll
        for (int i = 0; i < 4; i++) {
            const int idx = tx + i * 256;
            if (idx < 512) {
                const int g = idx >> 6, rem = idx & 63;
                cp16(sbase + idx * 16,
                     Ap + ((size_t)(m16g0 + g) * KT_A + kt) * 512 + rem * 8);
            } else {
                const int j = idx - 512;
                const int nb = j >> 7, rem = j & 127;
                cp16(sbase + idx * 16,
                     Bp + ((size_t)(n32g0 + nb) * KT_A + kt) * 1024 + rem * 8);
            }
        }
    };

    float acc[4][4][4];
    #pragma unroll
    for (int i = 0; i < 4; i++)
        #pragma unroll
        for (int j = 0; j < 4; j++)
            #pragma unroll
            for (int r = 0; r < 4; r++) acc[i][j][r] = 0.f;

    loadStage(0, 0); CP_COMMIT();
    loadStage(1, 1); CP_COMMIT();

    for (int kt = 0; kt < KT_A; kt++) {
        const int st = kt % 3;
        CP_WAIT1();
        __syncthreads();
        if (kt + 2 < KT_A) { loadStage(kt + 2, (kt + 2) % 3); CP_COMMIT(); }

        const __half* sf = smh + st * STG_HALFS;
        const __half* aB = sf + (warp >> 2) * 2048;
        const __half* bB = sf + 4096 + (warp & 3) * 1024;

        #pragma unroll
        for (int ks = 0; ks < 2; ks++) {
            uint32_t af[4][4];
            #pragma unroll
            for (int mt = 0; mt < 4; mt++) {
                uint4 t = *(const uint4*)(aB + mt * 512 + ks * 256 + lane * 8);
                af[mt][0] = t.x; af[mt][1] = t.y; af[mt][2] = t.z; af[mt][3] = t.w;
            }
            uint4 tb0 = *(const uint4*)(bB + ks * 512 + lane * 8);
            uint4 tb1 = *(const uint4*)(bB + ks * 512 + 256 + lane * 8);
            uint32_t bf[4][2];
            bf[0][0] = tb0.x; bf[0][1] = tb1.x;
            bf[1][0] = tb0.y; bf[1][1] = tb1.y;
            bf[2][0] = tb0.z; bf[2][1] = tb1.z;
            bf[3][0] = tb0.w; bf[3][1] = tb1.w;
            #pragma unroll
            for (int mt = 0; mt < 4; mt++)
                #pragma unroll
                for (int nt = 0; nt < 4; nt++)
                    mma_f16(acc[mt][nt], af[mt], bf[nt]);
        }
    }

    if (EPI == 3) {
        const int whichBlk = colBase >> 11;
        const int h = (colBase & 2047) >> 7;
        #pragma unroll
        for (int mt = 0; mt < 4; mt++) {
            #pragma unroll
            for (int nt = 0; nt < 4; nt++) {
                const int gn = colBase + wn + nt * 8 + 2 * lc;
                const int d  = gn & 127;
                const int m0 = rowBase + wm + mt * 16 + lr;
                const int b  = m0 >> 11, s = m0 & 2047;
                float* a = acc[mt][nt];
                const float v00 = a[0] + bias[gn], v01 = a[1] + bias[gn + 1];
                const float v10 = a[2] + bias[gn], v11 = a[3] + bias[gn + 1];
                if (whichBlk == 0) {
                    // Q flash-A-frags: [bh][s>>7][ (s>>4)&7 ][d>>4][lane][8]
                    __half* qp = Qf
                        + (((((size_t)(b * 16 + h) * 16 + (s >> 7)) * 8 + ((s >> 4) & 7)) * 8
                            + (d >> 4)) * 256) + lane * 8 + ((d >> 3) & 1) * 4;
                    *(__half2*)(qp)     = __floats2half2_rn(v00, v01);   // row s
                    *(__half2*)(qp + 2) = __floats2half2_rn(v10, v11);   // row s+8
                } else {
                    float* base = (whichBlk == 1) ? Ck : Cv;
                    *(float2*)&base[((((size_t)b * 16 + h) << 11) + s) * 128 + d] =
                        make_float2(v00, v01);
                    *(float2*)&base[((((size_t)b * 16 + h) << 11) + s + 8) * 128 + d] =
                        make_float2(v10, v11);
                    if (whichBlk == 1) {
                        // K flash-B-frags: blk + (d>>4)*1024 + (nt>>1)*256 + lane*8
                        //                  + (nt&1)*4 + ((d>>3)&1)*2
                        __half* kb = Kf + (((size_t)(b * 16 + h) * 32) + (s >> 6)) * 8192
                                   + (d >> 4) * 1024 + lane * 8 + ((d >> 3) & 1) * 2;
                        const int nt0 = (s & 63) >> 3;           // row s (even)
                        *(__half2*)(kb + (nt0 >> 1) * 256 + (nt0 & 1) * 4) =
                            __floats2half2_rn(v00, v01);
                        const int nt1 = nt0 + 1;                 // row s+8
                        *(__half2*)(kb + (nt1 >> 1) * 256 + (nt1 & 1) * 4) =
                            __floats2half2_rn(v10, v11);
                    } else {
                        const size_t vblk =
                            (((size_t)(b * 16 + h) * 32) + (s >> 6)) * 8192
                            + ((s & 63) >> 4) * 2048 + (d >> 4) * 256;
                        auto vst = [&](int ss, int dd, float val) {
                            const int la = (dd & 7) * 4 + ((ss >> 1) & 3);
                            Vf[vblk + la * 8 + ((dd >> 3) & 1) * 4
                               + ((ss & 15) >> 3) * 2 + (ss & 1)] = __float2half_rn(val);
                        };
                        vst(s, d, v00);     vst(s, d + 1, v01);
                        vst(s + 8, d, v10); vst(s + 8, d + 1, v11);
                    }
                }
            }
        }
        return;
    }

    #pragma unroll
    for (int mt = 0; mt < 4; mt++) {
        #pragma unroll
        for (int nt = 0; nt < 4; nt++) {
            const int gm = rowBase + wm + mt * 16 + lr;
            const int gn = colBase + wn + nt * 8 + 2 * lc;
            float* a = acc[mt][nt];
            #pragma unroll
            for (int r = 0; r < 2; r++)
                *(float2*)&C[(size_t)(gm + r * 8) * Ntot + gn] =
                    make_float2(a[r * 2 + 0], a[r * 2 + 1]);
        }
    }
}

// ---------------------------------------------------------------------------
// FP16 flash attention: frag-major K/V via cp.async, Q frags via LDG,
// P kept in registers. smem = K[2][8192] + V[2][8192] halfs = 64 KB.
// ---------------------------------------------------------------------------
#define FLASH_SMEM (4 * 8192 * 2)

__global__ void __launch_bounds__(256, 1) flash_kernel(
    const __half* __restrict__ qf, const __half* __restrict__ kf,
    const __half* __restrict__ vf, const float* __restrict__ mask,
    float* __restrict__ ctx, __half* __restrict__ ctxp, float scale)
{
    const int qi = gridDim.x - 1 - blockIdx.x;      // heavy tiles first
    const int rowBase = qi * 128;
    const int bh = blockIdx.y;
    const int b = bh >> 4, h = bh & 15;

    const __half* Kg = kf + (size_t)bh * 32 * 8192;
    const __half* Vg = vf + (size_t)bh * 32 * 8192;
    const float* mrow = mask + (size_t)b * S_;

    extern __shared__ __half smh[];
    const uint32_t smemU = (uint32_t)__cvta_generic_to_shared(smh);

    const int tx = threadIdx.x;
    const int lane = tx & 31, wid = tx >> 5;
    const int lr = lane >> 2, lc = lane & 3;
    const int r0g = rowBase + wid * 16 + lr;
    const int r1g = r0g + 8;

    // Q fragments: 8 LDG.128
    uint32_t qfr[8][4];
    {
        const __half* Qg = qf + (((size_t)bh * 16 + qi) * 8 + wid) * 2048 + lane * 8;
        #pragma unroll
        for (int ks = 0; ks < 8; ks++) {
            uint4 t = *(const uint4*)(Qg + ks * 256);
            qfr[ks][0] = t.x; qfr[ks][1] = t.y; qfr[ks][2] = t.z; qfr[ks][3] = t.w;
        }
    }

    const int jEnd = 2 * qi + 2;
    auto cpKV = [&](int j, int st) {
        const __half* ksrc = Kg + (size_t)j * 8192;
        const __half* vsrc = Vg + (size_t)j * 8192;
        const uint32_t kd = smemU + st * 16384;
        const uint32_t vd = smemU + 32768 + st * 16384;
        #pragma unroll
        for (int i = 0; i < 4; i++) {
            const int i8 = tx + i * 256;
            cp16(kd + i8 * 16, ksrc + i8 * 8);
            cp16(vd + i8 * 16, vsrc + i8 * 8);
        }
    };
    cpKV(0, 0); CP_COMMIT(); CP_WAIT0();
    __syncthreads();

    float oacc[16][4];
    #pragma unroll
    for (int i = 0; i < 16; i++)
        #pragma unroll
        for (int r = 0; r < 4; r++) oacc[i][r] = 0.f;
    float m0 = -1e30f, m1 = -1e30f, l0 = 0.f, l1 = 0.f;

    for (int j = 0; j < jEnd; j++) {
        const int st = j & 1;
        const bool more = (j + 1 < jEnd);
        if (more) { cpKV(j + 1, st ^ 1); CP_COMMIT(); }

        // ---- S = Q @ K^T ----
        float sacc[8][4];
        #pragma unroll
        for (int nt = 0; nt < 8; nt++)
            #pragma unroll
            for (int r = 0; r < 4; r++) sacc[nt][r] = 0.f;

        const __half* kb = smh + st * 8192;
        #pragma unroll
        for (int ks = 0; ks < 8; ks++) {
            #pragma unroll
            for (int np = 0; np < 4; np++) {
                uint4 t = *(const uint4*)(kb + ks * 1024 + np * 256 + lane * 8);
                uint32_t b0[2] = { t.x, t.y };
                uint32_t b1[2] = { t.z, t.w };
                mma_f16(sacc[2 * np],     qfr[ks], b0);
                mma_f16(sacc[2 * np + 1], qfr[ks], b1);
            }
        }

        // ---- scale + mask + causal + online softmax ----
        const int keyBase = j * 64;
        float mt0 = -1e30f, mt1 = -1e30f;
        #pragma unroll
        for (int nt = 0; nt < 8; nt++) {
            const int kcol = keyBase + nt * 8 + 2 * lc;
            float2 mk = *(const float2*)&mrow[kcol];
            float s0 = sacc[nt][0] * scale + mk.x;
            float s1 = sacc[nt][1] * scale + mk.y;
            float s2 = sacc[nt][2] * scale + mk.x;
            float s3 = sacc[nt][3] * scale + mk.y;
            if (kcol     > r0g) s0 = -10000.f;
            if (kcol + 1 > r0g) s1 = -10000.f;
            if (kcol     > r1g) s2 = -10000.f;
            if (kcol + 1 > r1g) s3 = -10000.f;
            sacc[nt][0] = s0; sacc[nt][1] = s1; sacc[nt][2] = s2; sacc[nt][3] = s3;
            mt0 = fmaxf(mt0, fmaxf(s0, s1));
            mt1 = fmaxf(mt1, fmaxf(s2, s3));
        }
        mt0 = fmaxf(mt0, __shfl_xor_sync(0xffffffffu, mt0, 1));
        mt0 = fmaxf(mt0, __shfl_xor_sync(0xffffffffu, mt0, 2));
        mt1 = fmaxf(mt1, __shfl_xor_sync(0xffffffffu, mt1, 1));
        mt1 = fmaxf(mt1, __shfl_xor_sync(0xffffffffu, mt1, 2));

        const float mn0 = fmaxf(m0, mt0), mn1 = fmaxf(m1, mt1);
        const float a0 = __expf(m0 - mn0), a1 = __expf(m1 - mn1);
        m0 = mn0; m1 = mn1;

        float ts0 = 0.f, ts1 = 0.f;
        #pragma unroll
        for (int nt = 0; nt < 8; nt++) {
            float p0 = __expf(sacc[nt][0] - mn0);
            float p1 = __expf(sacc[nt][1] - mn0);
            float p2 = __expf(sacc[nt][2] - mn1);
            float p3 = __expf(sacc[nt][3] - mn1);
            sacc[nt][0] = p0; sacc[nt][1] = p1; sacc[nt][2] = p2; sacc[nt][3] = p3;
            ts0 += p0 + p1;
            ts1 += p2 + p3;
        }
        ts0 += __shfl_xor_sync(0xffffffffu, ts0, 1);
        ts0 += __shfl_xor_sync(0xffffffffu, ts0, 2);
        ts1 += __shfl_xor_sync(0xffffffffu, ts1, 1);
        ts1 += __shfl_xor_sync(0xffffffffu, ts1, 2);
        l0 = l0 * a0 + ts0;
        l1 = l1 * a1 + ts1;

        #pragma unroll
        for (int nt = 0; nt < 16; nt++) {
            oacc[nt][0] *= a0; oacc[nt][1] *= a0;
            oacc[nt][2] *= a1; oacc[nt][3] *= a1;
        }

        // ---- O += P @ V (P converted to fp16 in-register) ----
        const __half* vb = smh + 16384 + st * 8192;
        #pragma unroll
        for (int ks = 0; ks < 4; ks++) {
            uint32_t af[4];
            af[0] = h2u(__floats2half2_rn(sacc[2 * ks][0],     sacc[2 * ks][1]));
            af[1] = h2u(__floats2half2_rn(sacc[2 * ks][2],     sacc[2 * ks][3]));
            af[2] = h2u(__floats2half2_rn(sacc[2 * ks + 1][0], sacc[2 * ks + 1][1]));
            af[3] = h2u(__floats2half2_rn(sacc[2 * ks + 1][2], sacc[2 * ks + 1][3]));
            #pragma unroll
            for (int np = 0; np < 8; np++) {
                uint4 t = *(const uint4*)(vb + ks * 2048 + np * 256 + lane * 8);
                uint32_t b0[2] = { t.x, t.y };
                uint32_t b1[2] = { t.z, t.w };
                mma_f16(oacc[2 * np],     af, b0);
                mma_f16(oacc[2 * np + 1], af, b1);
            }
        }

        if (more) { CP_WAIT0(); __syncthreads(); }
    }

    // ---- epilogue: exact ctx [B,S,H] + fp16 GEMM-A-frag copy ----
    const float inv0 = 1.0f / l0;
    const float inv1 = 1.0f / l1;
    const size_t o0 = ((size_t)b * S_ + r0g) * H_ + h * 128 + 2 * lc;
    const size_t o1 = ((size_t)b * S_ + r1g) * H_ + h * 128 + 2 * lc;
    const int mg = b * S_ + r0g;
    #pragma unroll
    for (int nt = 0; nt < 16; nt++) {
        float v0 = oacc[nt][0] * inv0, v1 = oacc[nt][1] * inv0;
        float v2 = oacc[nt][2] * inv1, v3 = oacc[nt][3] * inv1;
        *(float2*)(ctx + o0 + nt * 8) = make_float2(v0, v1);
        *(float2*)(ctx + o1 + nt * 8) = make_float2(v2, v3);
        const int k0 = h * 128 + nt * 8 + 2 * lc;
        __half2 h01 = __floats2half2_rn(v0, v1);
        __half2 h23 = __floats2half2_rn(v2, v3);
        uint2 u = make_uint2(h2u(h01), h2u(h23));
        *(uint2*)&ctxp[afragH(mg, k0)] = u;
    }
}

// ---------------------------------------------------------------------------
extern "C" void kernel_launch(void* const* d_in, const int* in_sizes, int n_in,
                              void* d_out, int out_size)
{
    const float* x    = (const float*)d_in[0];
    const float* mask = (const float*)d_in[1];
    const float* qkvw = (const float*)d_in[2];
    const float* qkvb = (const float*)d_in[3];
    const float* ow   = (const float*)d_in[4];
    const float* nw   = (const float*)d_in[5];
    const float* nb   = (const float*)d_in[6];

    float* out     = (float*)d_out;
    float* out_o   = out;
    float* out_k   = out + 1 * BSH;
    float* out_v   = out + 2 * BSH;
    float* out_ctx = out + 3 * BSH;
    float* out_ln  = out + 4 * BSH;

    __half *qfr, *kfr, *vfr, *lnp, *ctxp, *qkvwP, *owP;
    cudaGetSymbolAddress((void**)&qfr,   g_qfr);
    cudaGetSymbolAddress((void**)&kfr,   g_kfr);
    cudaGetSymbolAddress((void**)&vfr,   g_vfr);
    cudaGetSymbolAddress((void**)&lnp,   g_lnp);
    cudaGetSymbolAddress((void**)&ctxp,  g_ctxp);
    cudaGetSymbolAddress((void**)&qkvwP, g_qkvwP);
    cudaGetSymbolAddress((void**)&owP,   g_owP);

    cudaFuncSetAttribute(mma_gemm2<3>, cudaFuncAttributeMaxDynamicSharedMemorySize, GEMM_SMEM);
    cudaFuncSetAttribute(mma_gemm2<0>, cudaFuncAttributeMaxDynamicSharedMemorySize, GEMM_SMEM);
    cudaFuncSetAttribute(flash_kernel, cudaFuncAttributeMaxDynamicSharedMemorySize, FLASH_SMEM);

    const float scale = 1.0f / sqrtf((float)DH);

    prep_b<<<dim3(KT_A, 3 * H_ / 32), 256>>>(qkvw, qkvwP, 3 * H_);
    prep_b<<<dim3(KT_A, H_ / 32), 256>>>(ow, owP, H_);

    ln_kernel<<<B_ * S_, 256>>>(x, nw, nb, out_ln, lnp);

    mma_gemm2<3><<<dim3(48, 32), 256, GEMM_SMEM>>>(
        lnp, qkvwP, nullptr, qfr, out_k, out_v, kfr, vfr, qkvb, 3 * H_);

    flash_kernel<<<dim3(16, BH), 256, FLASH_SMEM>>>(
        qfr, kfr, vfr, mask, out_ctx, ctxp, scale);

    mma_gemm2<0><<<dim3(16, 32), 256, GEMM_SMEM>>>(
        ctxp, owP, out_o, nullptr, nullptr, nullptr, nullptr, nullptr, nullptr, H_);
}